// round 2
// baseline (speedup 1.0000x reference)
#include <cuda_runtime.h>
#include <cstdint>

// SSIM loss over NCHW (32,3,512,512) fp32 pair; 3x3 box filter, reflect pad 1,
// scalar mean output. Single fused pass: vertical 3-sum in registers (sliding
// window), horizontal 3-sum via shared memory, per-block partials reduced
// deterministically in a finalize kernel (fp64).

#define H 512
#define W 512
#define PLANES (32 * 3)
#define RPB 32                      // output rows per block
#define BLOCKS_X (H / RPB)          // 16
#define NBLOCKS (BLOCKS_X * PLANES) // 1536

__device__ float g_partials[NBLOCKS];

__device__ __forceinline__ int refl(int i) {
    // reflect pad of 1: -1 -> 1, 512 -> 510
    if (i < 0) return -i;
    if (i > H - 1) return 2 * (H - 1) - i;
    return i;
}

__global__ __launch_bounds__(512, 2)
void ssim_kernel(const float* __restrict__ x, const float* __restrict__ y) {
    const int plane = blockIdx.y;
    const int r0 = blockIdx.x * RPB;
    const int c = threadIdx.x; // 0..511

    const float* __restrict__ xp = x + (size_t)plane * H * W;
    const float* __restrict__ yp = y + (size_t)plane * H * W;

    __shared__ float sh[5][W + 2];

    const float C1 = 0.0001f;   // 0.01^2
    const float C2 = 0.0009f;   // 0.03^2
    const float inv9 = 1.0f / 9.0f;

    // register ring of the 5 quantities for rows (r-1, r)
    float p2[5], p1[5];
    {
        int rm1 = refl(r0 - 1);
        float xv = __ldg(&xp[rm1 * W + c]);
        float yv = __ldg(&yp[rm1 * W + c]);
        p2[0] = xv; p2[1] = yv; p2[2] = xv * xv; p2[3] = yv * yv; p2[4] = xv * yv;
        xv = __ldg(&xp[r0 * W + c]);
        yv = __ldg(&yp[r0 * W + c]);
        p1[0] = xv; p1[1] = yv; p1[2] = xv * xv; p1[3] = yv * yv; p1[4] = xv * yv;
    }

    float acc = 0.0f;

    for (int r = r0; r < r0 + RPB; ++r) {
        int rp1 = refl(r + 1);
        float xv = __ldg(&xp[rp1 * W + c]);
        float yv = __ldg(&yp[rp1 * W + c]);
        float cur[5];
        cur[0] = xv; cur[1] = yv; cur[2] = xv * xv; cur[3] = yv * yv; cur[4] = xv * yv;

        // vertical 3-sum for this column; write to shared with column-reflect halo
        #pragma unroll
        for (int q = 0; q < 5; ++q) {
            float v = p2[q] + p1[q] + cur[q];
            sh[q][c + 1] = v;
            if (c == 1)   sh[q][0]     = v;   // padded col -1 == col 1
            if (c == 510) sh[q][W + 1] = v;   // padded col 512 == col 510
        }
        __syncthreads();

        float s0 = sh[0][c] + sh[0][c + 1] + sh[0][c + 2];
        float s1 = sh[1][c] + sh[1][c + 1] + sh[1][c + 2];
        float s2 = sh[2][c] + sh[2][c + 1] + sh[2][c + 2];
        float s3 = sh[3][c] + sh[3][c + 1] + sh[3][c + 2];
        float s4 = sh[4][c] + sh[4][c + 1] + sh[4][c + 2];

        float mux = s0 * inv9;
        float muy = s1 * inv9;
        float sx  = s2 * inv9 - mux * mux;
        float sy  = s3 * inv9 - muy * muy;
        float sxy = s4 * inv9 - mux * muy;

        float n = (2.0f * mux * muy + C1) * (2.0f * sxy + C2);
        float d = (mux * mux + muy * muy + C1) * (sx + sy + C2);
        float v = (1.0f - n / d + 1e-20f) * 0.5f;
        v = fminf(fmaxf(v, 0.0f), 1.0f);
        acc += v;

        #pragma unroll
        for (int q = 0; q < 5; ++q) { p2[q] = p1[q]; p1[q] = cur[q]; }
        __syncthreads(); // protect shared before next row's writes
    }

    // block reduction (reuse a separate shared array)
    __shared__ float red[512];
    red[c] = acc;
    __syncthreads();
    #pragma unroll
    for (int stride = 256; stride > 0; stride >>= 1) {
        if (c < stride) red[c] += red[c + stride];
        __syncthreads();
    }
    if (c == 0) {
        g_partials[blockIdx.y * gridDim.x + blockIdx.x] = red[0];
    }
}

__global__ void finalize_kernel(float* __restrict__ out) {
    __shared__ double red[256];
    int t = threadIdx.x;
    double s = 0.0;
    for (int i = t; i < NBLOCKS; i += 256) s += (double)g_partials[i];
    red[t] = s;
    __syncthreads();
    #pragma unroll
    for (int stride = 128; stride > 0; stride >>= 1) {
        if (t < stride) red[t] += red[t + stride];
        __syncthreads();
    }
    if (t == 0) {
        const double total = (double)PLANES * H * W; // 25,165,824
        out[0] = (float)(red[0] / total);
    }
}

extern "C" void kernel_launch(void* const* d_in, const int* in_sizes, int n_in,
                              void* d_out, int out_size) {
    const float* x = (const float*)d_in[0];
    const float* y = (const float*)d_in[1];
    float* out = (float*)d_out;

    dim3 grid(BLOCKS_X, PLANES);
    ssim_kernel<<<grid, 512>>>(x, y);
    finalize_kernel<<<1, 256>>>(out);
}

// round 3
// speedup vs baseline: 2.2839x; 2.2839x over previous
#include <cuda_runtime.h>
#include <cstdint>

// SSIM loss, NCHW (32,3,512,512) fp32, 3x3 box filter, reflect pad 1, scalar mean.
// Fully register-resident: float4 per thread (4 cols), vertical 3-sum via 3-row
// register ring (3-phase unrolled), horizontal 3-sum via warp shuffles + halo
// column loads on lanes 0/31. No shared memory / barriers in the hot loop.
// Deterministic single-launch reduction via last-block ticket (fp64 final sum).

#define H 512
#define W 512
#define PLANES (32 * 3)
#define RPB 32
#define BLOCKS_X (H / RPB)           // 16
#define NBLOCKS (BLOCKS_X * PLANES)  // 1536

__device__ float g_partials[NBLOCKS];
__device__ unsigned int g_count = 0;

struct Row {
    float4 X, Y, XX, YY, XY;
    float hX, hY, hXX, hYY, hXY;  // halo column (meaningful on lanes 0 / 31)
};

__device__ __forceinline__ void load_row(Row& R,
                                         const float* __restrict__ xp,
                                         const float* __restrict__ yp,
                                         int rr, int base, int hcol, bool doHalo) {
    const float4 xv = *reinterpret_cast<const float4*>(xp + rr * W + base);
    const float4 yv = *reinterpret_cast<const float4*>(yp + rr * W + base);
    R.X = xv;
    R.Y = yv;
    R.XX = make_float4(xv.x * xv.x, xv.y * xv.y, xv.z * xv.z, xv.w * xv.w);
    R.YY = make_float4(yv.x * yv.x, yv.y * yv.y, yv.z * yv.z, yv.w * yv.w);
    R.XY = make_float4(xv.x * yv.x, xv.y * yv.y, xv.z * yv.z, xv.w * yv.w);
    if (doHalo) {
        float hx = __ldg(xp + rr * W + hcol);
        float hy = __ldg(yp + rr * W + hcol);
        R.hX = hx; R.hY = hy;
        R.hXX = hx * hx; R.hYY = hy * hy; R.hXY = hx * hy;
    }
}

__device__ __forceinline__ float ssim_px(float a, float b, float c, float d, float e) {
    const float C1f = 0.0001f, C2f = 0.0009f, inv9 = 1.0f / 9.0f;
    float mux = a * inv9, muy = b * inv9;
    float mxx = mux * mux, myy = muy * muy, mxy = mux * muy;
    float sx  = fmaf(c, inv9, -mxx);
    float sy  = fmaf(d, inv9, -myy);
    float sxy = fmaf(e, inv9, -mxy);
    float n   = fmaf(2.0f, mxy, C1f) * fmaf(2.0f, sxy, C2f);
    float den = (mxx + myy + C1f) * (sx + sy + C2f);
    float v   = (1.0f - __fdividef(n, den) + 1e-20f) * 0.5f;
    return __saturatef(v);
}

// Horizontal 3-sum of vertical sums for one quantity q.
#define HQ(q)                                                                     \
    float4 v_##q = make_float4(A.q.x + B.q.x + C.q.x, A.q.y + B.q.y + C.q.y,      \
                               A.q.z + B.q.z + C.q.z, A.q.w + B.q.w + C.q.w);     \
    float hv_##q = A.h##q + B.h##q + C.h##q;                                      \
    float lv_##q = __shfl_up_sync(0xffffffffu, v_##q.w, 1);                       \
    float rv_##q = __shfl_down_sync(0xffffffffu, v_##q.x, 1);                     \
    if (lane == 0)  lv_##q = (wseg == 0) ? v_##q.y : hv_##q;                      \
    if (lane == 31) rv_##q = (wseg == 3) ? v_##q.z : hv_##q;                      \
    float4 h_##q = make_float4(lv_##q + v_##q.x + v_##q.y,                        \
                               v_##q.x + v_##q.y + v_##q.z,                       \
                               v_##q.y + v_##q.z + v_##q.w,                       \
                               v_##q.z + v_##q.w + rv_##q);

__device__ __forceinline__ void emit(const Row& A, const Row& B, const Row& C,
                                     float& acc, int lane, int wseg) {
    HQ(X) HQ(Y) HQ(XX) HQ(YY) HQ(XY)
    acc += ssim_px(h_X.x, h_Y.x, h_XX.x, h_YY.x, h_XY.x);
    acc += ssim_px(h_X.y, h_Y.y, h_XX.y, h_YY.y, h_XY.y);
    acc += ssim_px(h_X.z, h_Y.z, h_XX.z, h_YY.z, h_XY.z);
    acc += ssim_px(h_X.w, h_Y.w, h_XX.w, h_YY.w, h_XY.w);
}

__global__ __launch_bounds__(128)
void ssim_main(const float* __restrict__ x, const float* __restrict__ y,
               float* __restrict__ out) {
    const int tid   = threadIdx.x;
    const int lane  = tid & 31;
    const int wseg  = tid >> 5;                 // 0..3, 128-col segment
    const int plane = blockIdx.y;
    const int r0    = blockIdx.x * RPB;

    const int segbase = wseg * 128;
    const int base    = segbase + lane * 4;
    const float* __restrict__ xp = x + (size_t)plane * H * W;
    const float* __restrict__ yp = y + (size_t)plane * H * W;

    // halo column: lane 0 needs col segbase-1 (or reflected col 1 at image edge,
    // value then overridden by own v.y); lane 31 needs col segbase+128 (or col 510).
    const int  hcol   = (lane == 0) ? ((wseg == 0) ? 1 : segbase - 1)
                                    : ((wseg == 3) ? 510 : segbase + 128);
    const bool doHalo = (lane == 0) || (lane == 31);

    Row ra, rb, rc;
    {
        int rm1 = (r0 == 0) ? 1 : (r0 - 1);
        load_row(ra, xp, yp, rm1, base, hcol, doHalo);
        load_row(rb, xp, yp, r0,  base, hcol, doHalo);
    }

    float acc = 0.0f;
    int r = r0;
    // 30 rows in 3-phase (ring copies rename away), then 2 tail rows.
    for (int i = 0; i < RPB - 2; i += 3) {
        load_row(rc, xp, yp, r + 1, base, hcol, doHalo);
        emit(ra, rb, rc, acc, lane, wseg); ++r;
        load_row(ra, xp, yp, r + 1, base, hcol, doHalo);
        emit(rb, rc, ra, acc, lane, wseg); ++r;
        load_row(rb, xp, yp, r + 1, base, hcol, doHalo);
        emit(rc, ra, rb, acc, lane, wseg); ++r;
    }
    load_row(rc, xp, yp, r + 1, base, hcol, doHalo);   // row r0+30 (loads r0+31)
    emit(ra, rb, rc, acc, lane, wseg); ++r;
    {
        int rlast = (r + 1 > H - 1) ? (H - 2) : (r + 1); // reflect: 512 -> 510
        load_row(ra, xp, yp, rlast, base, hcol, doHalo);
        emit(rb, rc, ra, acc, lane, wseg);               // row r0+31
    }

    // ---- block reduction (4 warps) ----
    #pragma unroll
    for (int o = 16; o > 0; o >>= 1)
        acc += __shfl_xor_sync(0xffffffffu, acc, o);

    __shared__ float wsum[4];
    __shared__ int   last_flag;
    if (lane == 0) wsum[wseg] = acc;
    __syncthreads();

    if (tid == 0) {
        float p = wsum[0] + wsum[1] + wsum[2] + wsum[3];
        g_partials[blockIdx.y * gridDim.x + blockIdx.x] = p;
        __threadfence();
        unsigned t = atomicAdd(&g_count, 1u);
        last_flag = (t == NBLOCKS - 1);
    }
    __syncthreads();

    // ---- last block: deterministic fp64 final sum ----
    if (last_flag) {
        double s = 0.0;
        for (int i = tid; i < NBLOCKS; i += 128)
            s += (double)__ldcg(&g_partials[i]);
        #pragma unroll
        for (int o = 16; o > 0; o >>= 1)
            s += __shfl_xor_sync(0xffffffffu, s, o);
        __shared__ double dsum[4];
        if (lane == 0) dsum[wseg] = s;
        __syncthreads();
        if (tid == 0) {
            double total = dsum[0] + dsum[1] + dsum[2] + dsum[3];
            out[0] = (float)(total / (double)((size_t)PLANES * H * W));
            g_count = 0;  // reset for next graph replay
        }
    }
}

extern "C" void kernel_launch(void* const* d_in, const int* in_sizes, int n_in,
                              void* d_out, int out_size) {
    const float* x = (const float*)d_in[0];
    const float* y = (const float*)d_in[1];
    float* out = (float*)d_out;

    dim3 grid(BLOCKS_X, PLANES);
    ssim_main<<<grid, 128>>>(x, y, out);
}

// round 4
// speedup vs baseline: 2.5842x; 1.1315x over previous
#include <cuda_runtime.h>
#include <cstdint>

// SSIM loss, NCHW (32,3,512,512) fp32, 3x3 box, reflect pad 1, scalar mean.
// R3: packed f32x2 math (Blackwell FADD2/FMUL2/FFMA2 via inline PTX) for the
// vertical sums, horizontal sums and SSIM core; scalar only for rcp.approx.
// Register ring (3-phase), shuffle-based column halo, last-block fp64 reduce.

#define H 512
#define W 512
#define PLANES (32 * 3)
#define RPB 32
#define BLOCKS_X (H / RPB)           // 16
#define NBLOCKS (BLOCKS_X * PLANES)  // 1536

typedef unsigned long long u64;

__device__ float g_partials[NBLOCKS];
__device__ unsigned int g_count = 0;

__device__ __forceinline__ u64 pk(float lo, float hi) {
    u64 r; asm("mov.b64 %0, {%1, %2};" : "=l"(r) : "f"(lo), "f"(hi)); return r;
}
__device__ __forceinline__ void unpk(u64 v, float& lo, float& hi) {
    asm("mov.b64 {%0, %1}, %2;" : "=f"(lo), "=f"(hi) : "l"(v));
}
__device__ __forceinline__ u64 add2(u64 a, u64 b) {
    u64 d; asm("add.rn.f32x2 %0, %1, %2;" : "=l"(d) : "l"(a), "l"(b)); return d;
}
__device__ __forceinline__ u64 sub2(u64 a, u64 b) {
    u64 d; asm("sub.rn.f32x2 %0, %1, %2;" : "=l"(d) : "l"(a), "l"(b)); return d;
}
__device__ __forceinline__ u64 mul2(u64 a, u64 b) {
    u64 d; asm("mul.rn.f32x2 %0, %1, %2;" : "=l"(d) : "l"(a), "l"(b)); return d;
}
__device__ __forceinline__ u64 fma2(u64 a, u64 b, u64 c) {
    u64 d; asm("fma.rn.f32x2 %0, %1, %2, %3;" : "=l"(d) : "l"(a), "l"(b), "l"(c)); return d;
}
__device__ __forceinline__ float rcpf(float x) {
    float r; asm("rcp.approx.ftz.f32 %0, %1;" : "=f"(r) : "f"(x)); return r;
}

struct Row {
    u64 X0, X1, Y0, Y1, XX0, XX1, YY0, YY1, XY0, XY1;
    float hX, hY, hXX, hYY, hXY;   // halo column (lanes 0/31 only)
};

struct K {
    u64 inv9p, twop, c1p, c2p, nhp, php;
};

__device__ __forceinline__ void load_row(Row& R,
                                         const float* __restrict__ xp,
                                         const float* __restrict__ yp,
                                         int rr, int base, int hcol, bool doHalo) {
    const float4 xv = *reinterpret_cast<const float4*>(xp + rr * W + base);
    const float4 yv = *reinterpret_cast<const float4*>(yp + rr * W + base);
    R.X0 = pk(xv.x, xv.y); R.X1 = pk(xv.z, xv.w);
    R.Y0 = pk(yv.x, yv.y); R.Y1 = pk(yv.z, yv.w);
    R.XX0 = mul2(R.X0, R.X0); R.XX1 = mul2(R.X1, R.X1);
    R.YY0 = mul2(R.Y0, R.Y0); R.YY1 = mul2(R.Y1, R.Y1);
    R.XY0 = mul2(R.X0, R.Y0); R.XY1 = mul2(R.X1, R.Y1);
    if (doHalo) {
        float hx = __ldg(xp + rr * W + hcol);
        float hy = __ldg(yp + rr * W + hcol);
        R.hX = hx; R.hY = hy;
        R.hXX = hx * hx; R.hYY = hy * hy; R.hXY = hx * hy;
    }
}

// SSIM for a packed pair of pixels; returns packed (0.5 - 0.5*n/d).
// Clamp dropped: d >= C1*C2 > 0 and |n| <= d up to rounding, so clipping only
// affects ulp-level cases (tolerance is 1e-3).
__device__ __forceinline__ u64 ssim2(u64 a, u64 b, u64 c, u64 d, u64 e, const K& k) {
    u64 mux = mul2(a, k.inv9p), muy = mul2(b, k.inv9p);
    u64 mxx = mul2(mux, mux), myy = mul2(muy, muy), mxy = mul2(mux, muy);
    u64 sx  = sub2(mul2(c, k.inv9p), mxx);
    u64 sy  = sub2(mul2(d, k.inv9p), myy);
    u64 sxy = sub2(mul2(e, k.inv9p), mxy);
    u64 n   = mul2(fma2(mxy, k.twop, k.c1p), fma2(sxy, k.twop, k.c2p));
    u64 den = mul2(add2(add2(mxx, myy), k.c1p), add2(add2(sx, sy), k.c2p));
    float d0, d1; unpk(den, d0, d1);
    u64 rp = pk(rcpf(d0), rcpf(d1));
    u64 q  = mul2(n, rp);
    return fma2(q, k.nhp, k.php);
}

// Vertical packed 3-sum for quantity q
#define VQ(q)                                                      \
    u64 v0_##q = add2(add2(A.q##0, B.q##0), C.q##0);               \
    u64 v1_##q = add2(add2(A.q##1, B.q##1), C.q##1);               \
    float hv_##q = A.h##q + B.h##q + C.h##q;

// Horizontal packed 3-sum: h0_ covers px (0,1), h1_ covers px (2,3)
#define HQ(q)                                                                 \
    float a0_##q, a1_##q, a2_##q, a3_##q;                                     \
    unpk(v0_##q, a0_##q, a1_##q);                                             \
    unpk(v1_##q, a2_##q, a3_##q);                                             \
    float lv_##q = __shfl_up_sync(0xffffffffu, a3_##q, 1);                    \
    float rv_##q = __shfl_down_sync(0xffffffffu, a0_##q, 1);                  \
    if (lane == 0)  lv_##q = (wseg == 0) ? a1_##q : hv_##q;                   \
    if (lane == 31) rv_##q = (wseg == 3) ? a2_##q : hv_##q;                   \
    u64 mid_##q = pk(a1_##q, a2_##q);                                         \
    u64 h0_##q = add2(add2(pk(lv_##q, a0_##q), v0_##q), mid_##q);             \
    u64 h1_##q = add2(add2(mid_##q, v1_##q), pk(a3_##q, rv_##q));

__device__ __forceinline__ void emit(const Row& A, const Row& B, const Row& C,
                                     u64& acc, int lane, int wseg, const K& k) {
    VQ(X) VQ(Y) VQ(XX) VQ(YY) VQ(XY)
    HQ(X) HQ(Y) HQ(XX) HQ(YY) HQ(XY)
    acc = add2(acc, ssim2(h0_X, h0_Y, h0_XX, h0_YY, h0_XY, k));
    acc = add2(acc, ssim2(h1_X, h1_Y, h1_XX, h1_YY, h1_XY, k));
}

__global__ __launch_bounds__(128)
void ssim_main(const float* __restrict__ x, const float* __restrict__ y,
               float* __restrict__ out) {
    const int tid   = threadIdx.x;
    const int lane  = tid & 31;
    const int wseg  = tid >> 5;                 // 0..3, 128-col segment
    const int plane = blockIdx.y;
    const int r0    = blockIdx.x * RPB;

    const int segbase = wseg * 128;
    const int base    = segbase + lane * 4;
    const float* __restrict__ xp = x + (size_t)plane * H * W;
    const float* __restrict__ yp = y + (size_t)plane * H * W;

    const int  hcol   = (lane == 0) ? ((wseg == 0) ? 1 : segbase - 1)
                                    : ((wseg == 3) ? 510 : segbase + 128);
    const bool doHalo = (lane == 0) || (lane == 31);

    K k;
    k.inv9p = pk(1.0f / 9.0f, 1.0f / 9.0f);
    k.twop  = pk(2.0f, 2.0f);
    k.c1p   = pk(0.0001f, 0.0001f);
    k.c2p   = pk(0.0009f, 0.0009f);
    k.nhp   = pk(-0.5f, -0.5f);
    k.php   = pk(0.5f, 0.5f);

    Row ra, rb, rc;
    {
        int rm1 = (r0 == 0) ? 1 : (r0 - 1);
        load_row(ra, xp, yp, rm1, base, hcol, doHalo);
        load_row(rb, xp, yp, r0,  base, hcol, doHalo);
    }

    u64 acc = pk(0.0f, 0.0f);
    int r = r0;
    for (int i = 0; i < RPB - 2; i += 3) {  // 30 rows, 3-phase ring
        load_row(rc, xp, yp, r + 1, base, hcol, doHalo);
        emit(ra, rb, rc, acc, lane, wseg, k); ++r;
        load_row(ra, xp, yp, r + 1, base, hcol, doHalo);
        emit(rb, rc, ra, acc, lane, wseg, k); ++r;
        load_row(rb, xp, yp, r + 1, base, hcol, doHalo);
        emit(rc, ra, rb, acc, lane, wseg, k); ++r;
    }
    load_row(rc, xp, yp, r + 1, base, hcol, doHalo);     // output row r0+30
    emit(ra, rb, rc, acc, lane, wseg, k); ++r;
    {
        int rlast = (r + 1 > H - 1) ? (H - 2) : (r + 1); // reflect 512 -> 510
        load_row(ra, xp, yp, rlast, base, hcol, doHalo);
        emit(rb, rc, ra, acc, lane, wseg, k);            // output row r0+31
    }

    // ---- block reduction ----
    float alo, ahi; unpk(acc, alo, ahi);
    float accf = alo + ahi;
    #pragma unroll
    for (int o = 16; o > 0; o >>= 1)
        accf += __shfl_xor_sync(0xffffffffu, accf, o);

    __shared__ float wsum[4];
    __shared__ int   last_flag;
    if (lane == 0) wsum[wseg] = accf;
    __syncthreads();

    if (tid == 0) {
        float p = wsum[0] + wsum[1] + wsum[2] + wsum[3];
        g_partials[blockIdx.y * gridDim.x + blockIdx.x] = p;
        __threadfence();
        unsigned t = atomicAdd(&g_count, 1u);
        last_flag = (t == NBLOCKS - 1);
    }
    __syncthreads();

    if (last_flag) {
        double s = 0.0;
        for (int i = tid; i < NBLOCKS; i += 128)
            s += (double)__ldcg(&g_partials[i]);
        #pragma unroll
        for (int o = 16; o > 0; o >>= 1)
            s += __shfl_xor_sync(0xffffffffu, s, o);
        __shared__ double dsum[4];
        if (lane == 0) dsum[wseg] = s;
        __syncthreads();
        if (tid == 0) {
            double total = dsum[0] + dsum[1] + dsum[2] + dsum[3];
            out[0] = (float)(total / (double)((size_t)PLANES * H * W));
            g_count = 0;  // reset for next graph replay
        }
    }
}

extern "C" void kernel_launch(void* const* d_in, const int* in_sizes, int n_in,
                              void* d_out, int out_size) {
    const float* x = (const float*)d_in[0];
    const float* y = (const float*)d_in[1];
    float* out = (float*)d_out;

    dim3 grid(BLOCKS_X, PLANES);
    ssim_main<<<grid, 128>>>(x, y, out);
}